// round 10
// baseline (speedup 1.0000x reference)
#include <cuda_runtime.h>

// Problem constants (fixed by the dataset)
#define B_   128
#define E_   100000
#define F_   5000
#define C_   8
#define DIN_ 10
#define DOUT_ 10
#define H_   (F_ * C_)
#define EPS_ 1e-5f

// Transposed scratch (static device mem). Together 102.4 MB -> fits 126 MB L2.
__device__ float g_xT[(size_t)E_ * B_];    // xT[e][b]
__device__ float g_outT[(size_t)E_ * B_];  // outT[e][b] = x + b3, scatter target

// ---------------------------------------------------------------------------
// Kernel A: high-MLP tiled transpose. Block (8,32) handles a 32e x 128b tile.
// ---------------------------------------------------------------------------
__global__ __launch_bounds__(256)
void transpose_init_kernel(const float* __restrict__ x,
                           const float* __restrict__ b3) {
    __shared__ float tile[32][129];           // tile[e_loc][b]
    const int e0 = blockIdx.x * 32;
    const int tx = threadIdx.x;               // 0..7
    const int ty = threadIdx.y;               // 0..31

#pragma unroll
    for (int j = 0; j < 4; j++) {
        const int b = ty + 32 * j;
        float4 v = __ldcs(reinterpret_cast<const float4*>(
                              x + (size_t)b * E_ + e0) + tx);
        tile[tx * 4 + 0][b] = v.x;
        tile[tx * 4 + 1][b] = v.y;
        tile[tx * 4 + 2][b] = v.z;
        tile[tx * 4 + 3][b] = v.w;
    }
    __syncthreads();
    {
        const int e = e0 + ty;
        const float bias = __ldg(b3 + e);
        const size_t row = (size_t)e * B_;
#pragma unroll
        for (int j = 0; j < 4; j++) {
            const int bb = 4 * (tx + 8 * j);
            float4 w;
            w.x = tile[ty][bb + 0];
            w.y = tile[ty][bb + 1];
            w.z = tile[ty][bb + 2];
            w.w = tile[ty][bb + 3];
            *reinterpret_cast<float4*>(&g_xT[row + bb]) = w;
            float4 w2;
            w2.x = w.x + bias; w2.y = w.y + bias;
            w2.z = w.z + bias; w2.w = w.w + bias;
            *reinterpret_cast<float4*>(&g_outT[row + bb]) = w2;
        }
    }
}

// ---------------------------------------------------------------------------
// Kernel D: high-MLP tiled transpose outT[e][b] -> out[b][e].
// ---------------------------------------------------------------------------
__global__ __launch_bounds__(256)
void transpose_out_kernel(float* __restrict__ out) {
    __shared__ float tile[32][129];           // tile[e_loc][b]
    const int e0 = blockIdx.x * 32;
    const int tx = threadIdx.x;
    const int ty = threadIdx.y;

    {
        const int e = e0 + ty;
        const size_t row = (size_t)e * B_;
#pragma unroll
        for (int j = 0; j < 4; j++) {
            const int bb = 4 * (tx + 8 * j);
            float4 v = __ldcs(reinterpret_cast<const float4*>(&g_outT[row + bb]));
            tile[ty][bb + 0] = v.x;
            tile[ty][bb + 1] = v.y;
            tile[ty][bb + 2] = v.z;
            tile[ty][bb + 3] = v.w;
        }
    }
    __syncthreads();
#pragma unroll
    for (int j = 0; j < 4; j++) {
        const int b = ty + 32 * j;
        float4 w;
        w.x = tile[tx * 4 + 0][b];
        w.y = tile[tx * 4 + 1][b];
        w.z = tile[tx * 4 + 2][b];
        w.w = tile[tx * 4 + 3][b];
        __stcs(reinterpret_cast<float4*>(out + (size_t)b * E_ + e0) + tx, w);
    }
}

// Fast ELU: MUFU.EX2-based.
__device__ __forceinline__ float elu1(float z) {
    return z > 0.0f ? z : __expf(z) - 1.0f;
}

// Vectorized global reduce-add, 8B per lane (sm_90+).
__device__ __forceinline__ void red_add_v2(float* addr, float a, float b) {
    asm volatile("red.global.add.v2.f32 [%0], {%1, %2};"
                 :: "l"(addr), "f"(a), "f"(b) : "memory");
}

// ---------------------------------------------------------------------------
// Kernel C: 2 function nodes per 128-thread block; 64 threads per f, each
// thread handles 2 batch elements (float2 gathers, red.v2 atomics).
// Gathers + s loads issue BEFORE the block barrier (indices loaded per-thread
// via broadcast __ldg), hiding the param-staging latency.
// ---------------------------------------------------------------------------
__global__ __launch_bounds__(B_)
void fn_node_kernel(const float* __restrict__ s,
                    const float* __restrict__ w1,
                    const float* __restrict__ b1,
                    const float* __restrict__ w2,
                    const float* __restrict__ b2,
                    const float* __restrict__ w3,
                    const int*   __restrict__ src1,   // in_e[f,d] = src1[(f*10+d)*8]
                    const int*   __restrict__ dst3,   // out_e[f,d] = dst3[(f*10+d)*8]
                    const float* __restrict__ g1,
                    const float* __restrict__ bt1,
                    const float* __restrict__ g2,
                    const float* __restrict__ bt2) {
    __shared__ float w1s[2][DIN_ * C_];
    __shared__ float w2s[2][C_ * C_];
    __shared__ float w3s[2][DOUT_ * C_];
    __shared__ int   oute[2][DOUT_];
    __shared__ float b1s[2][C_], b2s[2][C_];
    __shared__ float g1s[2][C_], bt1s[2][C_], g2s[2][C_], bt2s[2][C_];

    const int tid  = threadIdx.x;
    const int half = tid >> 6;            // which f in this block
    const int t    = tid & 63;
    const int f    = blockIdx.x * 2 + half;
    const int b0   = 2 * t;               // this thread covers batches b0, b0+1

    // ---- edge indices: warp-uniform broadcast loads (no smem, no barrier) ----
    int ine[DIN_];
#pragma unroll
    for (int d = 0; d < DIN_; d++) ine[d] = __ldg(&src1[(f * DIN_ + d) * C_]);

    // ---- gathers issue immediately: float2 per edge, MLP=10 ----
    float2 xv[DIN_];
#pragma unroll
    for (int d = 0; d < DIN_; d++)
        xv[d] = __ldg(reinterpret_cast<const float2*>(
                          &g_xT[(size_t)ine[d] * B_ + b0]));

    // ---- s loads for both batches, also before the barrier ----
    const float4* s0 = reinterpret_cast<const float4*>(
                           s + (size_t)b0 * H_ + f * C_);
    const float4* s1 = reinterpret_cast<const float4*>(
                           s + (size_t)(b0 + 1) * H_ + f * C_);
    float4 sA0 = __ldg(s0), sB0 = __ldg(s0 + 1);
    float4 sA1 = __ldg(s1), sB1 = __ldg(s1 + 1);

    // ---- cooperative param staging (latency hidden behind loads above) ----
#pragma unroll
    for (int k = t; k < DIN_ * C_; k += 64) w1s[half][k] = w1[f * (DIN_ * C_) + k];
    w2s[half][t] = w2[f * (C_ * C_) + t];
#pragma unroll
    for (int k = t; k < DOUT_ * C_; k += 64) w3s[half][k] = w3[f * (DOUT_ * C_) + k];
    if (t < DOUT_) oute[half][t] = dst3[(f * DOUT_ + t) * C_];
    if (t < C_) {
        int hc = f * C_ + t;
        b1s[half][t]  = b1[hc];
        b2s[half][t]  = b2[hc];
        g1s[half][t]  = g1[hc];
        bt1s[half][t] = bt1[hc];
        g2s[half][t]  = g2[hc];
        bt2s[half][t] = bt2[hc];
    }
    __syncthreads();

    float acc0[DOUT_], acc1[DOUT_];

    // ---- two passes: batch b0 (xv .x) and b0+1 (xv .y) ----
#pragma unroll
    for (int pass = 0; pass < 2; pass++) {
        float sv[C_];
        if (pass == 0) {
            sv[0]=sA0.x; sv[1]=sA0.y; sv[2]=sA0.z; sv[3]=sA0.w;
            sv[4]=sB0.x; sv[5]=sB0.y; sv[6]=sB0.z; sv[7]=sB0.w;
        } else {
            sv[0]=sA1.x; sv[1]=sA1.y; sv[2]=sA1.z; sv[3]=sA1.w;
            sv[4]=sB1.x; sv[5]=sB1.y; sv[6]=sB1.z; sv[7]=sB1.w;
        }

        // w1: 10x8 dense
        float h[C_];
#pragma unroll
        for (int c = 0; c < C_; c++) {
            float acc = b1s[half][c];
#pragma unroll
            for (int d = 0; d < DIN_; d++) {
                float xd = (pass == 0) ? xv[d].x : xv[d].y;
                acc = fmaf(xd, w1s[half][d * C_ + c], acc);
            }
            h[c] = acc;
        }

        // groupLN 1 + affine + elu(s*h)
        {
            float sum = 0.f, sq = 0.f;
#pragma unroll
            for (int c = 0; c < C_; c++) { sum += h[c]; sq += h[c] * h[c]; }
            float mu  = sum * 0.125f;
            float var = sq * 0.125f - mu * mu;
            float inv = rsqrtf(var + EPS_);
#pragma unroll
            for (int c = 0; c < C_; c++) {
                float z = (g1s[half][c] * ((h[c] - mu) * inv) + bt1s[half][c]) * sv[c];
                h[c] = elu1(z);
            }
        }

        // w2: 8x8 dense block
        float h2[C_];
#pragma unroll
        for (int c2 = 0; c2 < C_; c2++) {
            float acc = b2s[half][c2];
#pragma unroll
            for (int c = 0; c < C_; c++) acc = fmaf(h[c], w2s[half][c * C_ + c2], acc);
            h2[c2] = acc;
        }

        // groupLN 2 + affine + elu(h*s)
        {
            float sum = 0.f, sq = 0.f;
#pragma unroll
            for (int c = 0; c < C_; c++) { sum += h2[c]; sq += h2[c] * h2[c]; }
            float mu  = sum * 0.125f;
            float var = sq * 0.125f - mu * mu;
            float inv = rsqrtf(var + EPS_);
#pragma unroll
            for (int c = 0; c < C_; c++) {
                float z = (g2s[half][c] * ((h2[c] - mu) * inv) + bt2s[half][c]) * sv[c];
                h[c] = elu1(z);
            }
        }

        // w3 projection: 8 -> 10 per-edge contributions
#pragma unroll
        for (int d = 0; d < DOUT_; d++) {
            float acc = 0.f;
#pragma unroll
            for (int c = 0; c < C_; c++) acc = fmaf(h[c], w3s[half][d * C_ + c], acc);
            if (pass == 0) acc0[d] = acc; else acc1[d] = acc;
        }
    }

    // ---- vectorized scatter: one red.v2 per edge (b0, b0+1) ----
#pragma unroll
    for (int d = 0; d < DOUT_; d++)
        red_add_v2(&g_outT[(size_t)oute[half][d] * B_ + b0], acc0[d], acc1[d]);
}

// ---------------------------------------------------------------------------
// Launch
// ---------------------------------------------------------------------------
extern "C" void kernel_launch(void* const* d_in, const int* in_sizes, int n_in,
                              void* d_out, int out_size) {
    const float* x   = (const float*)d_in[0];
    const float* s   = (const float*)d_in[1];
    const float* w1  = (const float*)d_in[2];
    const float* b1  = (const float*)d_in[3];
    const float* w2  = (const float*)d_in[4];
    const float* b2  = (const float*)d_in[5];
    const float* w3  = (const float*)d_in[6];
    const float* b3  = (const float*)d_in[7];
    const float* g1  = (const float*)d_in[8];
    const float* bt1 = (const float*)d_in[9];
    const float* g2  = (const float*)d_in[10];
    const float* bt2 = (const float*)d_in[11];
    const int*   src1 = (const int*)d_in[12];
    const int*   dst3 = (const int*)d_in[17];
    float* out = (float*)d_out;

    dim3 tblk(8, 32);
    dim3 tgrid(E_ / 32, 1);   // each block covers 32 e x all 128 b
    transpose_init_kernel<<<tgrid, tblk>>>(x, b3);
    fn_node_kernel<<<F_ / 2, B_>>>(s, w1, b1, w2, b2, w3,
                                   src1, dst3, g1, bt1, g2, bt2);
    transpose_out_kernel<<<tgrid, tblk>>>(out);
}

// round 11
// speedup vs baseline: 1.0345x; 1.0345x over previous
#include <cuda_runtime.h>

// Problem constants (fixed by the dataset)
#define B_   128
#define E_   100000
#define F_   5000
#define C_   8
#define DIN_ 10
#define DOUT_ 10
#define H_   (F_ * C_)
#define EPS_ 1e-5f

// Transposed scratch (static device mem). Together 102.4 MB -> fits 126 MB L2.
__device__ float g_xT[(size_t)E_ * B_];    // xT[e][b]
__device__ float g_outT[(size_t)E_ * B_];  // outT[e][b] = x + b3, scatter target

// ---------------------------------------------------------------------------
// Kernel A: high-MLP tiled transpose. Block (8,32) handles a 32e x 128b tile.
// ---------------------------------------------------------------------------
__global__ __launch_bounds__(256)
void transpose_init_kernel(const float* __restrict__ x,
                           const float* __restrict__ b3) {
    __shared__ float tile[32][129];           // tile[e_loc][b]
    const int e0 = blockIdx.x * 32;
    const int tx = threadIdx.x;               // 0..7
    const int ty = threadIdx.y;               // 0..31

#pragma unroll
    for (int j = 0; j < 4; j++) {
        const int b = ty + 32 * j;
        float4 v = __ldcs(reinterpret_cast<const float4*>(
                              x + (size_t)b * E_ + e0) + tx);
        tile[tx * 4 + 0][b] = v.x;
        tile[tx * 4 + 1][b] = v.y;
        tile[tx * 4 + 2][b] = v.z;
        tile[tx * 4 + 3][b] = v.w;
    }
    __syncthreads();
    {
        const int e = e0 + ty;
        const float bias = __ldg(b3 + e);
        const size_t row = (size_t)e * B_;
#pragma unroll
        for (int j = 0; j < 4; j++) {
            const int bb = 4 * (tx + 8 * j);
            float4 w;
            w.x = tile[ty][bb + 0];
            w.y = tile[ty][bb + 1];
            w.z = tile[ty][bb + 2];
            w.w = tile[ty][bb + 3];
            *reinterpret_cast<float4*>(&g_xT[row + bb]) = w;
            float4 w2;
            w2.x = w.x + bias; w2.y = w.y + bias;
            w2.z = w.z + bias; w2.w = w.w + bias;
            *reinterpret_cast<float4*>(&g_outT[row + bb]) = w2;
        }
    }
}

// ---------------------------------------------------------------------------
// Kernel D: high-MLP tiled transpose outT[e][b] -> out[b][e].
// ---------------------------------------------------------------------------
__global__ __launch_bounds__(256)
void transpose_out_kernel(float* __restrict__ out) {
    __shared__ float tile[32][129];           // tile[e_loc][b]
    const int e0 = blockIdx.x * 32;
    const int tx = threadIdx.x;
    const int ty = threadIdx.y;

    {
        const int e = e0 + ty;
        const size_t row = (size_t)e * B_;
#pragma unroll
        for (int j = 0; j < 4; j++) {
            const int bb = 4 * (tx + 8 * j);
            float4 v = __ldcs(reinterpret_cast<const float4*>(&g_outT[row + bb]));
            tile[ty][bb + 0] = v.x;
            tile[ty][bb + 1] = v.y;
            tile[ty][bb + 2] = v.z;
            tile[ty][bb + 3] = v.w;
        }
    }
    __syncthreads();
#pragma unroll
    for (int j = 0; j < 4; j++) {
        const int b = ty + 32 * j;
        float4 w;
        w.x = tile[tx * 4 + 0][b];
        w.y = tile[tx * 4 + 1][b];
        w.z = tile[tx * 4 + 2][b];
        w.w = tile[tx * 4 + 3][b];
        __stcs(reinterpret_cast<float4*>(out + (size_t)b * E_ + e0) + tx, w);
    }
}

// Fast ELU: MUFU.EX2-based.
__device__ __forceinline__ float elu1(float z) {
    return z > 0.0f ? z : __expf(z) - 1.0f;
}

// Vectorized global reduce-add, 16B per lane (sm_90+).
__device__ __forceinline__ void red_add_v4(float* addr, float a, float b,
                                           float c, float d) {
    asm volatile("red.global.add.v4.f32 [%0], {%1, %2, %3, %4};"
                 :: "l"(addr), "f"(a), "f"(b), "f"(c), "f"(d)
                 : "memory");
}

// ---------------------------------------------------------------------------
// Kernel C (R9 shape — proven best): one block per f, one thread per batch b.
// ONLY change vs R9: scatter staged in smem, issued as red.v4 (4x fewer
// atomic ops at the LTS atomic ALU); s loads use __ldcs (single-use).
// ---------------------------------------------------------------------------
__global__ __launch_bounds__(B_)
void fn_node_kernel(const float* __restrict__ s,
                    const float* __restrict__ w1,
                    const float* __restrict__ b1,
                    const float* __restrict__ w2,
                    const float* __restrict__ b2,
                    const float* __restrict__ w3,
                    const int*   __restrict__ src1,   // in_e[f,d] = src1[(f*10+d)*8]
                    const int*   __restrict__ dst3,   // out_e[f,d] = dst3[(f*10+d)*8]
                    const float* __restrict__ g1,
                    const float* __restrict__ bt1,
                    const float* __restrict__ g2,
                    const float* __restrict__ bt2) {
    __shared__ float w1s[DIN_ * C_];
    __shared__ float w2s[C_ * C_];
    __shared__ float w3s[DOUT_ * C_];
    __shared__ int   ine[DIN_];
    __shared__ int   oute[DOUT_];
    __shared__ float b1s[C_], b2s[C_], g1s[C_], bt1s[C_], g2s[C_], bt2s[C_];
    __shared__ __align__(16) float sc[DOUT_][B_];   // scatter staging (5 KB)

    const int f   = blockIdx.x;
    const int tid = threadIdx.x;   // == batch index b
    const int b   = tid;

    // ---- issue s loads FIRST (single-use -> streaming) ----
    const float4* srow = reinterpret_cast<const float4*>(s + (size_t)b * H_ + f * C_);
    float4 sa = __ldcs(srow);
    float4 sb = __ldcs(srow + 1);

    if (tid < DIN_ * C_)  w1s[tid] = w1[f * (DIN_ * C_) + tid];
    if (tid < C_ * C_)    w2s[tid] = w2[f * (C_ * C_) + tid];
    if (tid < DOUT_ * C_) w3s[tid] = w3[f * (DOUT_ * C_) + tid];
    if (tid < DIN_)       ine[tid]  = src1[(f * DIN_ + tid) * C_];
    if (tid < DOUT_)      oute[tid] = dst3[(f * DOUT_ + tid) * C_];
    if (tid < C_) {
        int hc = f * C_ + tid;
        b1s[tid]  = b1[hc];
        b2s[tid]  = b2[hc];
        g1s[tid]  = g1[hc];
        bt1s[tid] = bt1[hc];
        g2s[tid]  = g2[hc];
        bt2s[tid] = bt2[hc];
    }
    __syncthreads();

    // ---- gather from transposed x: fully coalesced, MLP=10 ----
    float xv[DIN_];
#pragma unroll
    for (int d = 0; d < DIN_; d++) xv[d] = __ldg(&g_xT[(size_t)ine[d] * B_ + b]);

    float sv[C_] = {sa.x, sa.y, sa.z, sa.w, sb.x, sb.y, sb.z, sb.w};

    // ---- w1: 10x8 dense ----
    float h[C_];
#pragma unroll
    for (int c = 0; c < C_; c++) {
        float acc = b1s[c];
#pragma unroll
        for (int d = 0; d < DIN_; d++) acc = fmaf(xv[d], w1s[d * C_ + c], acc);
        h[c] = acc;
    }

    // ---- groupLN 1 + affine + elu(s*h) ----
    {
        float sum = 0.f, sq = 0.f;
#pragma unroll
        for (int c = 0; c < C_; c++) { sum += h[c]; sq += h[c] * h[c]; }
        float mu  = sum * 0.125f;
        float var = sq * 0.125f - mu * mu;
        float inv = rsqrtf(var + EPS_);
#pragma unroll
        for (int c = 0; c < C_; c++) {
            float z = (g1s[c] * ((h[c] - mu) * inv) + bt1s[c]) * sv[c];
            h[c] = elu1(z);
        }
    }

    // ---- w2: 8x8 dense block ----
    float h2[C_];
#pragma unroll
    for (int c2 = 0; c2 < C_; c2++) {
        float acc = b2s[c2];
#pragma unroll
        for (int c = 0; c < C_; c++) acc = fmaf(h[c], w2s[c * C_ + c2], acc);
        h2[c2] = acc;
    }

    // ---- groupLN 2 + affine + elu(h*s) ----
    {
        float sum = 0.f, sq = 0.f;
#pragma unroll
        for (int c = 0; c < C_; c++) { sum += h2[c]; sq += h2[c] * h2[c]; }
        float mu  = sum * 0.125f;
        float var = sq * 0.125f - mu * mu;
        float inv = rsqrtf(var + EPS_);
#pragma unroll
        for (int c = 0; c < C_; c++) {
            float z = (g2s[c] * ((h2[c] - mu) * inv) + bt2s[c]) * sv[c];
            h[c] = elu1(z);
        }
    }

    // ---- w3: 8 -> 10, stage per-edge contributions in smem ----
#pragma unroll
    for (int d = 0; d < DOUT_; d++) {
        float acc = 0.f;
#pragma unroll
        for (int c = 0; c < C_; c++) acc = fmaf(h[c], w3s[d * C_ + c], acc);
        sc[d][b] = acc;
    }
    __syncthreads();

    // ---- vectorized scatter: 10 edges x 32 red.v4 lanes (4x fewer L2 atomics) ----
#pragma unroll
    for (int i = tid; i < DOUT_ * 32; i += B_) {
        int d = i >> 5;
        int l = i & 31;
        const float* v = &sc[d][l * 4];
        red_add_v4(&g_outT[(size_t)oute[d] * B_ + l * 4], v[0], v[1], v[2], v[3]);
    }
}

// ---------------------------------------------------------------------------
// Launch
// ---------------------------------------------------------------------------
extern "C" void kernel_launch(void* const* d_in, const int* in_sizes, int n_in,
                              void* d_out, int out_size) {
    const float* x   = (const float*)d_in[0];
    const float* s   = (const float*)d_in[1];
    const float* w1  = (const float*)d_in[2];
    const float* b1  = (const float*)d_in[3];
    const float* w2  = (const float*)d_in[4];
    const float* b2  = (const float*)d_in[5];
    const float* w3  = (const float*)d_in[6];
    const float* b3  = (const float*)d_in[7];
    const float* g1  = (const float*)d_in[8];
    const float* bt1 = (const float*)d_in[9];
    const float* g2  = (const float*)d_in[10];
    const float* bt2 = (const float*)d_in[11];
    const int*   src1 = (const int*)d_in[12];
    const int*   dst3 = (const int*)d_in[17];
    float* out = (float*)d_out;

    dim3 tblk(8, 32);
    dim3 tgrid(E_ / 32, 1);   // each block covers 32 e x all 128 b
    transpose_init_kernel<<<tgrid, tblk>>>(x, b3);
    fn_node_kernel<<<F_, B_>>>(s, w1, b1, w2, b2, w3,
                               src1, dst3, g1, bt1, g2, bt2);
    transpose_out_kernel<<<tgrid, tblk>>>(out);
}